// round 3
// baseline (speedup 1.0000x reference)
#include <cuda_runtime.h>
#include <cstdint>
#include <cstddef>

constexpr int BATCH = 4, SEQ = 2048, DI = 4096, DO = 4096, RANK = 16;
constexpr int MTOT = BATCH * SEQ;          // 8192
constexpr float LORA_SCALE = 2.0f;         // ALPHA / RANK

constexpr int TM = 128, TN = 128, KC = 32; // K-chunk = 32 fp32 = 128B rows
constexpr int STAGES = 3;
constexpr int NCHUNK = DI / KC;            // 128 real chunks; chunk 128 = LoRA chunk
constexpr int A_BYTES = TM * 128;          // 16 KB
constexpr int B_BYTES = TN * 128;          // 16 KB
constexpr int STAGE_BYTES = A_BYTES + B_BYTES;      // 32 KB
constexpr int SMEM_BYTES = 1024 + STAGES * STAGE_BYTES; // 99328

// ---------------- scratch (__device__ globals: allocation-free) -------------
// All stored tf32-rounded AND pair-interleaved along K in groups of 8:
// position layout per 8-group: [c0 c4 c1 c5 c2 c6 c3 c7]
__device__ __align__(128) float g_xp[(size_t)MTOT * DI];
__device__ __align__(128) float g_wp[(size_t)DO * DI];
__device__ __align__(128) float g_downw[BATCH * RANK * DI];     // plain, scale folded
__device__ __align__(128) float g_upp[(size_t)BATCH * DO * 32]; // K padded to 32, perm
__device__ __align__(128) float g_lrp[(size_t)MTOT * 32];       // K padded to 32, perm

#define DEVFN __device__ __forceinline__

DEVFN float rna_tf32(float x) {
    uint32_t u;
    asm("cvt.rna.tf32.f32 %0, %1;" : "=r"(u) : "f"(x));
    return __uint_as_float(u);
}
DEVFN uint32_t s2u(const void* p) {
    uint32_t a;
    asm("{ .reg .u64 t; cvta.to.shared.u64 t, %1; cvt.u32.u64 %0, t; }" : "=r"(a) : "l"(p));
    return a;
}
DEVFN void cp_async16(uint32_t dst, const float* src) {
    unsigned long long g = (unsigned long long)__cvta_generic_to_global((void*)src);
    asm volatile("cp.async.cg.shared.global [%0], [%1], 16;" :: "r"(dst), "l"(g));
}
#define CP_COMMIT() asm volatile("cp.async.commit_group;" ::: "memory")

DEVFN void lds_v2(float& x, float& y, uint32_t addr) {
    asm volatile("ld.shared.v2.f32 {%0,%1}, [%2];" : "=f"(x), "=f"(y) : "r"(addr));
}

// D += A*B, m16n8k8 tf32 (fp32 accum). Operand regs already tf32-rounded bits.
DEVFN void mma8(float* d, float a0, float a1, float a2, float a3, float b0, float b1) {
    asm volatile("mma.sync.aligned.m16n8k8.row.col.f32.tf32.tf32.f32 "
                 "{%0,%1,%2,%3}, {%4,%5,%6,%7}, {%8,%9}, {%0,%1,%2,%3};"
                 : "+f"(d[0]), "+f"(d[1]), "+f"(d[2]), "+f"(d[3])
                 : "r"(__float_as_uint(a0)), "r"(__float_as_uint(a1)),
                   "r"(__float_as_uint(a2)), "r"(__float_as_uint(a3)),
                   "r"(__float_as_uint(b0)), "r"(__float_as_uint(b1)));
}

// ------------------------------- prep kernels -------------------------------
// down[b][r][i] = scale * sum_a down_aux[i,a] * hyper_down[b,a,r]
__global__ void prep_down_kernel(const float* __restrict__ da, const float* __restrict__ hd) {
    int idx = blockIdx.x * blockDim.x + threadIdx.x;
    if (idx >= BATCH * RANK * DI) return;
    int i = idx & (DI - 1);
    int r = (idx / DI) & (RANK - 1);
    int b = idx / (DI * RANK);
    float s = 0.f;
    #pragma unroll 8
    for (int a = 0; a < 64; a++)
        s += da[i * 64 + a] * hd[b * 1024 + a * 16 + r];
    g_downw[idx] = LORA_SCALE * s;
}

// up permuted: g_upp[b][o][pos]; pos<16 real (src rank per inverse perm), else 0
__global__ void prep_up_kernel(const float* __restrict__ ua, const float* __restrict__ hu) {
    int idx = blockIdx.x * blockDim.x + threadIdx.x;
    if (idx >= BATCH * DO * 32) return;
    int c = idx & 31;
    int o = (idx >> 5) & (DO - 1);
    int b = idx >> 17;
    float v = 0.f;
    if (c < 16) {
        int src_r = (c & 8) + ((c & 7) >> 1) + ((c & 1) << 2);
        float s = 0.f;
        #pragma unroll 8
        for (int a = 0; a < 64; a++)
            s += ua[a * DO + o] * hu[b * 1024 + src_r * 64 + a];
        v = rna_tf32(s);
    }
    g_upp[idx] = v;
}

// W -> tf32 + pair-interleaved permute (per 8-group)
__global__ void convw_kernel(const float4* __restrict__ W) {
    const int n = DO * DI / 8;
    for (int i = blockIdx.x * blockDim.x + threadIdx.x; i < n; i += gridDim.x * blockDim.x) {
        float4 v0 = W[2 * i], v1 = W[2 * i + 1];
        v0.x = rna_tf32(v0.x); v0.y = rna_tf32(v0.y); v0.z = rna_tf32(v0.z); v0.w = rna_tf32(v0.w);
        v1.x = rna_tf32(v1.x); v1.y = rna_tf32(v1.y); v1.z = rna_tf32(v1.z); v1.w = rna_tf32(v1.w);
        float4 o0 = make_float4(v0.x, v1.x, v0.y, v1.y);
        float4 o1 = make_float4(v0.z, v1.z, v0.w, v1.w);
        reinterpret_cast<float4*>(g_wp)[2 * i]     = o0;
        reinterpret_cast<float4*>(g_wp)[2 * i + 1] = o1;
    }
}

// Fused: x -> tf32+permute copy AND low_rank = x @ down^T (scale in down),
// stored permuted+padded into g_lrp.
__global__ __launch_bounds__(256) void lowrank_kernel(const float* __restrict__ x) {
    __shared__ float down_s[16 * 512];
    const int m0 = blockIdx.x * 32;
    const int bb = m0 / SEQ;
    const int t = threadIdx.x, w = t >> 5, l = t & 31;
    const int rowbase = m0 + w * 4;
    const float* dwb = g_downw + (size_t)bb * RANK * DI;

    float acc[4][16];
    #pragma unroll
    for (int j = 0; j < 4; j++)
        #pragma unroll
        for (int r = 0; r < 16; r++) acc[j][r] = 0.f;

    for (int k0 = 0; k0 < DI; k0 += 512) {
        __syncthreads();
        for (int j = t; j < 16 * 512; j += 256) {
            int r = j >> 9, kk = j & 511;
            down_s[j] = dwb[r * DI + k0 + kk];
        }
        __syncthreads();
        // each lane handles whole 8-groups: ks = l*8, stride 256 (2 iters)
        for (int ks = l * 8; ks < 512; ks += 256) {
            const int gk = k0 + ks;
            #pragma unroll
            for (int j = 0; j < 4; j++) {
                const float* xr = x + (size_t)(rowbase + j) * DI + gk;
                float4 v0 = *reinterpret_cast<const float4*>(xr);
                float4 v1 = *reinterpret_cast<const float4*>(xr + 4);
                v0.x = rna_tf32(v0.x); v0.y = rna_tf32(v0.y); v0.z = rna_tf32(v0.z); v0.w = rna_tf32(v0.w);
                v1.x = rna_tf32(v1.x); v1.y = rna_tf32(v1.y); v1.z = rna_tf32(v1.z); v1.w = rna_tf32(v1.w);
                float* op = g_xp + (size_t)(rowbase + j) * DI + gk;
                *reinterpret_cast<float4*>(op)     = make_float4(v0.x, v1.x, v0.y, v1.y);
                *reinterpret_cast<float4*>(op + 4) = make_float4(v0.z, v1.z, v0.w, v1.w);
                #pragma unroll
                for (int r = 0; r < 16; r++) {
                    const float* dr = down_s + r * 512 + ks;
                    float4 d0 = *reinterpret_cast<const float4*>(dr);
                    float4 d1 = *reinterpret_cast<const float4*>(dr + 4);
                    acc[j][r] += v0.x * d0.x + v0.y * d0.y + v0.z * d0.z + v0.w * d0.w
                               + v1.x * d1.x + v1.y * d1.y + v1.z * d1.z + v1.w * d1.w;
                }
            }
        }
    }
    #pragma unroll
    for (int j = 0; j < 4; j++) {
        #pragma unroll
        for (int r = 0; r < 16; r++) {
            float v = acc[j][r];
            v += __shfl_xor_sync(~0u, v, 16);
            v += __shfl_xor_sync(~0u, v, 8);
            v += __shfl_xor_sync(~0u, v, 4);
            v += __shfl_xor_sync(~0u, v, 2);
            v += __shfl_xor_sync(~0u, v, 1);
            if (l == 0) {
                int pos = (r & 8) + ((r & 3) << 1) + ((r >> 2) & 1);
                g_lrp[(size_t)(rowbase + j) * 32 + pos] = rna_tf32(v);
            }
        }
        if (l < 16) g_lrp[(size_t)(rowbase + j) * 32 + 16 + l] = 0.f;
    }
}

// ------------------------------- main GEMM ----------------------------------
DEVFN void load_stage(int chunk, uint32_t sA, int m0, int n0, int bb) {
    const uint32_t sB = sA + A_BYTES;
    const int t = threadIdx.x;
    const float* ap;
    const float* bp;
    size_t stride;
    if (chunk < NCHUNK) {
        ap = g_xp + (size_t)m0 * DI + chunk * KC;
        bp = g_wp + (size_t)n0 * DI + chunk * KC;
        stride = DI;
    } else {
        ap = g_lrp + (size_t)m0 * 32;
        bp = g_upp + ((size_t)bb * DO + n0) * 32;
        stride = 32;
    }
    #pragma unroll
    for (int q = 0; q < 4; q++) {
        int idx = t + q * 256;               // 0..1023
        int row = idx >> 3, ch = idx & 7;
        uint32_t dst = row * 128 + (uint32_t)((ch ^ (row & 7)) << 4);
        const float* src = ap + (size_t)row * stride + ch * 4;
        cp_async16(sA + dst, src);
        const float* srcb = bp + (size_t)row * stride + ch * 4;
        cp_async16(sB + dst, srcb);
    }
}

__global__ void __launch_bounds__(256, 2)
gemm_kernel(const float* __restrict__ bias, float* __restrict__ out) {
    extern __shared__ char smem_raw[];
    float* bias_s = reinterpret_cast<float*>(smem_raw);   // 128 floats
    const uint32_t stage_u = s2u(smem_raw + 1024);

    const int t = threadIdx.x;
    const int wid = t >> 5, lane = t & 31;
    const int gID = lane >> 2, g = lane & 3;
    const int warpM = wid >> 2, warpN = wid & 3;          // 2 x 4

    const int n0 = blockIdx.x * TN;
    const int m0 = blockIdx.y * TM;
    const int bb = m0 / SEQ;

    if (t < TN) bias_s[t] = bias[n0 + t];

    float acc[4][4][4];
    #pragma unroll
    for (int mf = 0; mf < 4; mf++)
        #pragma unroll
        for (int nf = 0; nf < 4; nf++)
            #pragma unroll
            for (int k = 0; k < 4; k++) acc[mf][nf][k] = 0.f;

    load_stage(0, stage_u + 0 * STAGE_BYTES, m0, n0, bb); CP_COMMIT();
    load_stage(1, stage_u + 1 * STAGE_BYTES, m0, n0, bb); CP_COMMIT();

    for (int c = 0; c <= NCHUNK; c++) {
        if (c < NCHUNK) asm volatile("cp.async.wait_group 1;" ::: "memory");
        else            asm volatile("cp.async.wait_group 0;" ::: "memory");
        __syncthreads();
        if (c + 2 <= NCHUNK) {
            load_stage(c + 2, stage_u + ((c + 2) % STAGES) * STAGE_BYTES, m0, n0, bb);
            CP_COMMIT();
        }
        const uint32_t sAc = stage_u + (c % STAGES) * STAGE_BYTES;
        const uint32_t sBc = sAc + A_BYTES;
        #pragma unroll
        for (int ks = 0; ks < 4; ks++) {
            const uint32_t cw = (uint32_t)(((ks << 1) | (g >> 1))); // 16B chunk pre-XOR
            const uint32_t half = (uint32_t)((g & 1) << 3);
            float bfr[4][2];
            #pragma unroll
            for (int nf = 0; nf < 4; nf++) {
                int row = warpN * 32 + nf * 8 + gID;
                uint32_t ad = sBc + row * 128 + ((cw ^ (uint32_t)(row & 7)) << 4) + half;
                lds_v2(bfr[nf][0], bfr[nf][1], ad);
            }
            #pragma unroll
            for (int mf = 0; mf < 4; mf++) {
                int row0 = warpM * 64 + mf * 16 + gID;
                int row1 = row0 + 8;
                uint32_t a0d = sAc + row0 * 128 + ((cw ^ (uint32_t)(row0 & 7)) << 4) + half;
                uint32_t a1d = sAc + row1 * 128 + ((cw ^ (uint32_t)(row1 & 7)) << 4) + half;
                float a0, a1, a2, a3;
                lds_v2(a0, a2, a0d);
                lds_v2(a1, a3, a1d);
                #pragma unroll
                for (int nf = 0; nf < 4; nf++)
                    mma8(acc[mf][nf], a0, a1, a2, a3, bfr[nf][0], bfr[nf][1]);
            }
        }
    }

    // epilogue: D layout c0:(gID, 2g) c1:(gID, 2g+1) c2:(gID+8, 2g) c3:(gID+8, 2g+1)
    #pragma unroll
    for (int mf = 0; mf < 4; mf++) {
        const int r0 = m0 + warpM * 64 + mf * 16 + gID;
        #pragma unroll
        for (int nf = 0; nf < 4; nf++) {
            const int col = warpN * 32 + nf * 8 + 2 * g;
            const float b0 = bias_s[col], b1 = bias_s[col + 1];
            float2 v0, v1;
            v0.x = acc[mf][nf][0] + b0; v0.y = acc[mf][nf][1] + b1;
            v1.x = acc[mf][nf][2] + b0; v1.y = acc[mf][nf][3] + b1;
            *reinterpret_cast<float2*>(out + (size_t)r0 * DO + n0 + col) = v0;
            *reinterpret_cast<float2*>(out + (size_t)(r0 + 8) * DO + n0 + col) = v1;
        }
    }
}

// ------------------------------- launch -------------------------------------
extern "C" void kernel_launch(void* const* d_in, const int* /*in_sizes*/, int /*n_in*/,
                              void* d_out, int /*out_size*/) {
    const float* x  = (const float*)d_in[0];
    const float* W  = (const float*)d_in[1];
    const float* b  = (const float*)d_in[2];
    const float* da = (const float*)d_in[3];
    const float* ua = (const float*)d_in[4];
    const float* hd = (const float*)d_in[5];
    const float* hu = (const float*)d_in[6];
    float* out = (float*)d_out;

    cudaFuncSetAttribute(gemm_kernel, cudaFuncAttributeMaxDynamicSharedMemorySize, SMEM_BYTES);

    prep_down_kernel<<<BATCH * RANK * DI / 256, 256>>>(da, hd);
    prep_up_kernel<<<BATCH * DO * 32 / 256, 256>>>(ua, hu);
    convw_kernel<<<2048, 256>>>(reinterpret_cast<const float4*>(W));
    lowrank_kernel<<<MTOT / 32, 256>>>(x);
    gemm_kernel<<<dim3(DO / TN, MTOT / TM), 256, SMEM_BYTES>>>(b, out);
}

// round 4
// speedup vs baseline: 1.0649x; 1.0649x over previous
#include <cuda_runtime.h>
#include <cstdint>
#include <cstddef>

constexpr int BATCH = 4, SEQ = 2048, DI = 4096, DO = 4096, RANK = 16;
constexpr int MTOT = BATCH * SEQ;          // 8192
constexpr float LORA_SCALE = 2.0f;         // ALPHA / RANK

constexpr int TM = 128, TN = 256, KC = 32; // K-chunk = 32 fp32 = 128B rows
constexpr int STAGES = 4;
constexpr int NCHUNK = DI / KC;            // 128 real chunks; chunk 128 = LoRA chunk
constexpr int A_BYTES = TM * 128;          // 16 KB
constexpr int B_BYTES = TN * 128;          // 32 KB
constexpr int STAGE_BYTES = A_BYTES + B_BYTES;           // 48 KB
constexpr int SMEM_BYTES = 1024 + STAGES * STAGE_BYTES;  // 197632

// Row swizzle over 16B chunk index (3 bits), conflict-free for v4 frag loads.
#define SWZ(r) (((((r) & 1) << 2) | (((r) >> 1) & 3)))

// ---------------- scratch (__device__ globals: allocation-free) -------------
// All tensors tf32-rounded AND transpose-interleaved per 16-k group:
// stored pos p holds original k = (p%4)*4 + p/4  (4x4 transpose, self-inverse)
__device__ __align__(128) float g_xp[(size_t)MTOT * DI];
__device__ __align__(128) float g_wp[(size_t)DO * DI];
__device__ __align__(128) float g_downw[BATCH * RANK * DI];     // plain, scale folded
__device__ __align__(128) float g_upp[(size_t)BATCH * DO * 32]; // K padded 32, perm
__device__ __align__(128) float g_lrp[(size_t)MTOT * 32];       // K padded 32, perm

#define DEVFN __device__ __forceinline__

DEVFN float rna_tf32(float x) {
    uint32_t u;
    asm("cvt.rna.tf32.f32 %0, %1;" : "=r"(u) : "f"(x));
    return __uint_as_float(u);
}
DEVFN uint32_t s2u(const void* p) {
    uint32_t a;
    asm("{ .reg .u64 t; cvta.to.shared.u64 t, %1; cvt.u32.u64 %0, t; }" : "=r"(a) : "l"(p));
    return a;
}
DEVFN void cp_async16(uint32_t dst, const float* src) {
    unsigned long long g = (unsigned long long)__cvta_generic_to_global((void*)src);
    asm volatile("cp.async.cg.shared.global [%0], [%1], 16;" :: "r"(dst), "l"(g));
}
#define CP_COMMIT() asm volatile("cp.async.commit_group;" ::: "memory")

DEVFN float4 lds_v4(uint32_t addr) {
    float4 v;
    asm volatile("ld.shared.v4.f32 {%0,%1,%2,%3}, [%4];"
                 : "=f"(v.x), "=f"(v.y), "=f"(v.z), "=f"(v.w) : "r"(addr));
    return v;
}

// D += A*B, m16n8k8 tf32 (fp32 accum). Operands already tf32-rounded bits.
DEVFN void mma8(float* d, float a0, float a1, float a2, float a3, float b0, float b1) {
    asm volatile("mma.sync.aligned.m16n8k8.row.col.f32.tf32.tf32.f32 "
                 "{%0,%1,%2,%3}, {%4,%5,%6,%7}, {%8,%9}, {%0,%1,%2,%3};"
                 : "+f"(d[0]), "+f"(d[1]), "+f"(d[2]), "+f"(d[3])
                 : "r"(__float_as_uint(a0)), "r"(__float_as_uint(a1)),
                   "r"(__float_as_uint(a2)), "r"(__float_as_uint(a3)),
                   "r"(__float_as_uint(b0)), "r"(__float_as_uint(b1)));
}

// ------------------------------- prep kernels -------------------------------
// down[b][r][i] = scale * sum_a down_aux[i,a] * hyper_down[b,a,r]
__global__ void prep_down_kernel(const float* __restrict__ da, const float* __restrict__ hd) {
    int idx = blockIdx.x * blockDim.x + threadIdx.x;
    if (idx >= BATCH * RANK * DI) return;
    int i = idx & (DI - 1);
    int r = (idx / DI) & (RANK - 1);
    int b = idx / (DI * RANK);
    float s = 0.f;
    #pragma unroll 8
    for (int a = 0; a < 64; a++)
        s += da[i * 64 + a] * hd[b * 1024 + a * 16 + r];
    g_downw[idx] = LORA_SCALE * s;
}

// up permuted: pos c<16 real (src rank = transpose inverse), else 0
__global__ void prep_up_kernel(const float* __restrict__ ua, const float* __restrict__ hu) {
    int idx = blockIdx.x * blockDim.x + threadIdx.x;
    if (idx >= BATCH * DO * 32) return;
    int c = idx & 31;
    int o = (idx >> 5) & (DO - 1);
    int b = idx >> 17;
    float v = 0.f;
    if (c < 16) {
        int src_r = (c & 3) * 4 + (c >> 2);
        float s = 0.f;
        #pragma unroll 8
        for (int a = 0; a < 64; a++)
            s += ua[a * DO + o] * hu[b * 1024 + src_r * 64 + a];
        v = rna_tf32(s);
    }
    g_upp[idx] = v;
}

DEVFN void transpose_store_16(float* op, float4 v0, float4 v1, float4 v2, float4 v3) {
    reinterpret_cast<float4*>(op)[0] = make_float4(v0.x, v1.x, v2.x, v3.x);
    reinterpret_cast<float4*>(op)[1] = make_float4(v0.y, v1.y, v2.y, v3.y);
    reinterpret_cast<float4*>(op)[2] = make_float4(v0.z, v1.z, v2.z, v3.z);
    reinterpret_cast<float4*>(op)[3] = make_float4(v0.w, v1.w, v2.w, v3.w);
}
DEVFN float4 rna4(float4 v) {
    v.x = rna_tf32(v.x); v.y = rna_tf32(v.y); v.z = rna_tf32(v.z); v.w = rna_tf32(v.w);
    return v;
}

// W -> tf32 + 16-group transpose interleave
__global__ void convw_kernel(const float4* __restrict__ W) {
    const int n = DO * DI / 16;
    for (int i = blockIdx.x * blockDim.x + threadIdx.x; i < n; i += gridDim.x * blockDim.x) {
        float4 v0 = rna4(W[4 * i + 0]);
        float4 v1 = rna4(W[4 * i + 1]);
        float4 v2 = rna4(W[4 * i + 2]);
        float4 v3 = rna4(W[4 * i + 3]);
        transpose_store_16(g_wp + (size_t)i * 16, v0, v1, v2, v3);
    }
}

// Fused: x -> tf32+perm copy AND low_rank = x @ down^T (scale folded in down).
// 16 rows per block, 8 warps x 2 rows.
__global__ __launch_bounds__(256) void lowrank_kernel(const float* __restrict__ x) {
    __shared__ float down_s[16 * 512];
    const int m0 = blockIdx.x * 16;
    const int bb = m0 / SEQ;
    const int t = threadIdx.x, w = t >> 5, l = t & 31;
    const int rowbase = m0 + w * 2;
    const float* dwb = g_downw + (size_t)bb * RANK * DI;

    float acc[2][16];
    #pragma unroll
    for (int j = 0; j < 2; j++)
        #pragma unroll
        for (int r = 0; r < 16; r++) acc[j][r] = 0.f;

    for (int k0 = 0; k0 < DI; k0 += 512) {
        __syncthreads();
        for (int j = t; j < 16 * 512; j += 256) {
            int r = j >> 9, kk = j & 511;
            down_s[j] = dwb[r * DI + k0 + kk];
        }
        __syncthreads();
        const int ks = l * 16;     // one 16-group per lane per 512-block
        const int gk = k0 + ks;
        #pragma unroll
        for (int j = 0; j < 2; j++) {
            const float* xr = x + (size_t)(rowbase + j) * DI + gk;
            float4 v0 = rna4(*reinterpret_cast<const float4*>(xr));
            float4 v1 = rna4(*reinterpret_cast<const float4*>(xr + 4));
            float4 v2 = rna4(*reinterpret_cast<const float4*>(xr + 8));
            float4 v3 = rna4(*reinterpret_cast<const float4*>(xr + 12));
            transpose_store_16(g_xp + (size_t)(rowbase + j) * DI + gk, v0, v1, v2, v3);
            #pragma unroll
            for (int r = 0; r < 16; r++) {
                const float* dr = down_s + r * 512 + ks;
                float4 d0 = *reinterpret_cast<const float4*>(dr);
                float4 d1 = *reinterpret_cast<const float4*>(dr + 4);
                float4 d2 = *reinterpret_cast<const float4*>(dr + 8);
                float4 d3 = *reinterpret_cast<const float4*>(dr + 12);
                acc[j][r] += v0.x * d0.x + v0.y * d0.y + v0.z * d0.z + v0.w * d0.w
                           + v1.x * d1.x + v1.y * d1.y + v1.z * d1.z + v1.w * d1.w
                           + v2.x * d2.x + v2.y * d2.y + v2.z * d2.z + v2.w * d2.w
                           + v3.x * d3.x + v3.y * d3.y + v3.z * d3.z + v3.w * d3.w;
            }
        }
    }
    #pragma unroll
    for (int j = 0; j < 2; j++) {
        #pragma unroll
        for (int r = 0; r < 16; r++) {
            float v = acc[j][r];
            v += __shfl_xor_sync(~0u, v, 16);
            v += __shfl_xor_sync(~0u, v, 8);
            v += __shfl_xor_sync(~0u, v, 4);
            v += __shfl_xor_sync(~0u, v, 2);
            v += __shfl_xor_sync(~0u, v, 1);
            if (l == 0) {
                int pos = (r & 3) * 4 + (r >> 2);
                g_lrp[(size_t)(rowbase + j) * 32 + pos] = rna_tf32(v);
            }
        }
        if (l < 16) g_lrp[(size_t)(rowbase + j) * 32 + 16 + l] = 0.f;
    }
}

// ------------------------------- main GEMM ----------------------------------
DEVFN void load_stage(int chunk, uint32_t sA, int m0, int n0, int bb) {
    const uint32_t sB = sA + A_BYTES;
    const int t = threadIdx.x;
    const float *ap, *bp;
    size_t str;
    if (chunk < NCHUNK) {
        ap = g_xp + (size_t)m0 * DI + chunk * KC;
        bp = g_wp + (size_t)n0 * DI + chunk * KC;
        str = DI;
    } else {
        ap = g_lrp + (size_t)m0 * 32;
        bp = g_upp + ((size_t)bb * DO + n0) * 32;
        str = 32;
    }
    #pragma unroll
    for (int q = 0; q < 2; q++) {                       // A: 1024 chunks16
        int idx = t + q * 512, row = idx >> 3, ch = idx & 7;
        cp_async16(sA + row * 128 + (uint32_t)((ch ^ SWZ(row)) << 4),
                   ap + (size_t)row * str + ch * 4);
    }
    #pragma unroll
    for (int q = 0; q < 4; q++) {                       // B: 2048 chunks16
        int idx = t + q * 512, row = idx >> 3, ch = idx & 7;
        cp_async16(sB + row * 128 + (uint32_t)((ch ^ SWZ(row)) << 4),
                   bp + (size_t)row * str + ch * 4);
    }
}

__global__ void __launch_bounds__(512, 1)
gemm_kernel(const float* __restrict__ bias, float* __restrict__ out) {
    extern __shared__ char smem_raw[];
    float* bias_s = reinterpret_cast<float*>(smem_raw);   // 256 floats
    const uint32_t stage_u = s2u(smem_raw + 1024);

    const int t = threadIdx.x;
    const int wid = t >> 5, lane = t & 31;
    const int gID = lane >> 2, g = lane & 3;
    const int warpM = wid >> 2, warpN = wid & 3;          // 4 x 4 warps

    const int n0 = blockIdx.x * TN;
    const int m0 = blockIdx.y * TM;
    const int bb = m0 / SEQ;

    if (t < TN) bias_s[t] = bias[n0 + t];

    float acc[2][8][4];
    #pragma unroll
    for (int mf = 0; mf < 2; mf++)
        #pragma unroll
        for (int nf = 0; nf < 8; nf++)
            #pragma unroll
            for (int k = 0; k < 4; k++) acc[mf][nf][k] = 0.f;

    load_stage(0, stage_u + 0 * STAGE_BYTES, m0, n0, bb); CP_COMMIT();
    load_stage(1, stage_u + 1 * STAGE_BYTES, m0, n0, bb); CP_COMMIT();
    load_stage(2, stage_u + 2 * STAGE_BYTES, m0, n0, bb); CP_COMMIT();

    for (int c = 0; c <= NCHUNK; c++) {
        int rem = NCHUNK - c;
        if (rem >= 2)      asm volatile("cp.async.wait_group 2;" ::: "memory");
        else if (rem == 1) asm volatile("cp.async.wait_group 1;" ::: "memory");
        else               asm volatile("cp.async.wait_group 0;" ::: "memory");
        __syncthreads();
        if (c + 3 <= NCHUNK) {
            load_stage(c + 3, stage_u + ((c + 3) & 3) * STAGE_BYTES, m0, n0, bb);
            CP_COMMIT();
        }
        const uint32_t sAc = stage_u + (c & 3) * STAGE_BYTES;
        const uint32_t sBc = sAc + A_BYTES;
        #pragma unroll
        for (int G = 0; G < 2; G++) {
            const uint32_t cw = (uint32_t)(4 * G + g);
            float4 Af[2][2];
            #pragma unroll
            for (int mf = 0; mf < 2; mf++)
                #pragma unroll
                for (int rr = 0; rr < 2; rr++) {
                    int row = warpM * 32 + mf * 16 + rr * 8 + gID;
                    Af[mf][rr] = lds_v4(sAc + row * 128 + ((cw ^ SWZ(row)) << 4));
                }
            #pragma unroll
            for (int half = 0; half < 2; half++) {
                float4 Bf[4];
                #pragma unroll
                for (int j = 0; j < 4; j++) {
                    int row = warpN * 64 + (half * 4 + j) * 8 + gID;
                    Bf[j] = lds_v4(sBc + row * 128 + ((cw ^ SWZ(row)) << 4));
                }
                #pragma unroll
                for (int mf = 0; mf < 2; mf++)
                    #pragma unroll
                    for (int j = 0; j < 4; j++) {
                        float* d = acc[mf][half * 4 + j];
                        mma8(d, Af[mf][0].x, Af[mf][1].x, Af[mf][0].y, Af[mf][1].y,
                             Bf[j].x, Bf[j].y);
                        mma8(d, Af[mf][0].z, Af[mf][1].z, Af[mf][0].w, Af[mf][1].w,
                             Bf[j].z, Bf[j].w);
                    }
            }
        }
    }

    // epilogue: c0:(gID, 2g) c1:(gID, 2g+1) c2:(gID+8, 2g) c3:(gID+8, 2g+1)
    #pragma unroll
    for (int mf = 0; mf < 2; mf++) {
        const int r0 = m0 + warpM * 32 + mf * 16 + gID;
        #pragma unroll
        for (int nf = 0; nf < 8; nf++) {
            const int col = warpN * 64 + nf * 8 + 2 * g;
            const float b0 = bias_s[col], b1 = bias_s[col + 1];
            float2 v0, v1;
            v0.x = acc[mf][nf][0] + b0; v0.y = acc[mf][nf][1] + b1;
            v1.x = acc[mf][nf][2] + b0; v1.y = acc[mf][nf][3] + b1;
            *reinterpret_cast<float2*>(out + (size_t)r0 * DO + n0 + col) = v0;
            *reinterpret_cast<float2*>(out + (size_t)(r0 + 8) * DO + n0 + col) = v1;
        }
    }
}

// ------------------------------- launch -------------------------------------
extern "C" void kernel_launch(void* const* d_in, const int* /*in_sizes*/, int /*n_in*/,
                              void* d_out, int /*out_size*/) {
    const float* x  = (const float*)d_in[0];
    const float* W  = (const float*)d_in[1];
    const float* b  = (const float*)d_in[2];
    const float* da = (const float*)d_in[3];
    const float* ua = (const float*)d_in[4];
    const float* hd = (const float*)d_in[5];
    const float* hu = (const float*)d_in[6];
    float* out = (float*)d_out;

    cudaFuncSetAttribute(gemm_kernel, cudaFuncAttributeMaxDynamicSharedMemorySize, SMEM_BYTES);

    prep_down_kernel<<<BATCH * RANK * DI / 256, 256>>>(da, hd);
    prep_up_kernel<<<BATCH * DO * 32 / 256, 256>>>(ua, hu);
    convw_kernel<<<4096, 256>>>(reinterpret_cast<const float4*>(W));
    lowrank_kernel<<<MTOT / 16, 256>>>(x);
    gemm_kernel<<<dim3(DO / TN, MTOT / TM), 512, SMEM_BYTES>>>(b, out);
}

// round 5
// speedup vs baseline: 1.1136x; 1.0457x over previous
#include <cuda_runtime.h>
#include <cstdint>
#include <cstddef>

constexpr int BATCH = 4, SEQ = 2048, DI = 4096, DO = 4096, RANK = 16;
constexpr int MTOT = BATCH * SEQ;          // 8192
constexpr float LORA_SCALE = 2.0f;         // ALPHA / RANK

constexpr int TM = 128, TN = 256, KC = 32; // K-chunk = 32 fp32 = 128B rows
constexpr int STAGES = 4;
constexpr int NCHUNK = DI / KC;            // 128 real chunks; chunk 128 = LoRA chunk
constexpr int A_BYTES = TM * 128;          // 16 KB
constexpr int B_BYTES = TN * 128;          // 32 KB
constexpr int STAGE_BYTES = A_BYTES + B_BYTES;           // 48 KB
constexpr int SMEM_BYTES = 1024 + STAGES * STAGE_BYTES;  // 197632

// Row swizzle over 16B chunk index (3 bits), conflict-free for v4 frag loads.
#define SWZ(r) (((((r) & 1) << 2) | (((r) >> 1) & 3)))

// ---------------- scratch (__device__ globals: allocation-free) -------------
// All tensors tf32-rounded AND transpose-interleaved per 16-k group:
// stored pos p holds original k = (p%4)*4 + p/4  (4x4 transpose, self-inverse)
__device__ __align__(128) float g_xp[(size_t)MTOT * DI];
__device__ __align__(128) float g_wp[(size_t)DO * DI];
__device__ __align__(128) float g_downw[BATCH * RANK * DI];     // plain, scale folded
__device__ __align__(128) float g_upp[(size_t)BATCH * DO * 32]; // K padded 32, perm
__device__ __align__(128) float g_lrp[(size_t)MTOT * 32];       // K padded 32, perm

#define DEVFN __device__ __forceinline__

DEVFN float rna_tf32(float x) {
    uint32_t u;
    asm("cvt.rna.tf32.f32 %0, %1;" : "=r"(u) : "f"(x));
    return __uint_as_float(u);
}
DEVFN uint32_t s2u(const void* p) {
    uint32_t a;
    asm("{ .reg .u64 t; cvta.to.shared.u64 t, %1; cvt.u32.u64 %0, t; }" : "=r"(a) : "l"(p));
    return a;
}
DEVFN void cp_async16(uint32_t dst, const float* src) {
    unsigned long long g = (unsigned long long)__cvta_generic_to_global((void*)src);
    asm volatile("cp.async.cg.shared.global [%0], [%1], 16;" :: "r"(dst), "l"(g));
}
#define CP_COMMIT() asm volatile("cp.async.commit_group;" ::: "memory")

DEVFN float4 lds_v4(uint32_t addr) {
    float4 v;
    asm volatile("ld.shared.v4.f32 {%0,%1,%2,%3}, [%4];"
                 : "=f"(v.x), "=f"(v.y), "=f"(v.z), "=f"(v.w) : "r"(addr));
    return v;
}

// D += A*B, m16n8k8 tf32 (fp32 accum). Operands already tf32-rounded bits.
DEVFN void mma8(float* d, float a0, float a1, float a2, float a3, float b0, float b1) {
    asm volatile("mma.sync.aligned.m16n8k8.row.col.f32.tf32.tf32.f32 "
                 "{%0,%1,%2,%3}, {%4,%5,%6,%7}, {%8,%9}, {%0,%1,%2,%3};"
                 : "+f"(d[0]), "+f"(d[1]), "+f"(d[2]), "+f"(d[3])
                 : "r"(__float_as_uint(a0)), "r"(__float_as_uint(a1)),
                   "r"(__float_as_uint(a2)), "r"(__float_as_uint(a3)),
                   "r"(__float_as_uint(b0)), "r"(__float_as_uint(b1)));
}

DEVFN void transpose_store_16(float* op, float4 v0, float4 v1, float4 v2, float4 v3) {
    reinterpret_cast<float4*>(op)[0] = make_float4(v0.x, v1.x, v2.x, v3.x);
    reinterpret_cast<float4*>(op)[1] = make_float4(v0.y, v1.y, v2.y, v3.y);
    reinterpret_cast<float4*>(op)[2] = make_float4(v0.z, v1.z, v2.z, v3.z);
    reinterpret_cast<float4*>(op)[3] = make_float4(v0.w, v1.w, v2.w, v3.w);
}
DEVFN float4 rna4(float4 v) {
    v.x = rna_tf32(v.x); v.y = rna_tf32(v.y); v.z = rna_tf32(v.z); v.w = rna_tf32(v.w);
    return v;
}

// ------------------------- merged prep kernel -------------------------------
// blocks [0,1024): down factors; [1024,3072): up factors; [3072,7168): W conv
__global__ __launch_bounds__(256) void prep_all_kernel(
    const float* __restrict__ da, const float* __restrict__ ua,
    const float* __restrict__ hd, const float* __restrict__ hu,
    const float4* __restrict__ W)
{
    const int bid = blockIdx.x, t = threadIdx.x;
    if (bid < 1024) {
        // down[b][r][i] = scale * sum_a da[i,a] * hd[b,a,r]
        int idx = bid * 256 + t;
        int i = idx & (DI - 1);
        int r = (idx / DI) & (RANK - 1);
        int b = idx / (DI * RANK);
        float s = 0.f;
        #pragma unroll 8
        for (int a = 0; a < 64; a++)
            s += da[i * 64 + a] * hd[b * 1024 + a * 16 + r];
        g_downw[idx] = LORA_SCALE * s;
    } else if (bid < 3072) {
        // up permuted: pos c<16 real (src rank = transpose inverse), else 0
        int idx = (bid - 1024) * 256 + t;
        int c = idx & 31;
        int o = (idx >> 5) & (DO - 1);
        int b = idx >> 17;
        float v = 0.f;
        if (c < 16) {
            int src_r = (c & 3) * 4 + (c >> 2);
            float s = 0.f;
            #pragma unroll 8
            for (int a = 0; a < 64; a++)
                s += ua[a * DO + o] * hu[b * 1024 + src_r * 64 + a];
            v = rna_tf32(s);
        }
        g_upp[idx] = v;
    } else {
        // W -> tf32 + 16-group transpose interleave (one 16-group per thread)
        int i = (bid - 3072) * 256 + t;
        float4 v0 = rna4(W[4 * i + 0]);
        float4 v1 = rna4(W[4 * i + 1]);
        float4 v2 = rna4(W[4 * i + 2]);
        float4 v3 = rna4(W[4 * i + 3]);
        transpose_store_16(g_wp + (size_t)i * 16, v0, v1, v2, v3);
    }
}

// smem swizzle for down_s: XOR 16B-chunk index with (chunk>>3)&7
DEVFN int dswz(int kk) {
    int c = kk >> 2;
    return ((c ^ ((c >> 3) & 7)) << 2) | (kk & 3);
}

// Fused: x -> tf32+perm copy AND low_rank = x @ down^T (scale folded in down).
__global__ __launch_bounds__(256) void lowrank_kernel(const float* __restrict__ x) {
    __shared__ float down_s[16 * 512];
    const int m0 = blockIdx.x * 16;
    const int bb = m0 / SEQ;
    const int t = threadIdx.x, w = t >> 5, l = t & 31;
    const int rowbase = m0 + w * 2;
    const float* dwb = g_downw + (size_t)bb * RANK * DI;

    const int ks = l * 16;
    const int o0 = dswz(ks), o1 = dswz(ks + 4), o2 = dswz(ks + 8), o3 = dswz(ks + 12);

    float acc[2][16];
    #pragma unroll
    for (int j = 0; j < 2; j++)
        #pragma unroll
        for (int r = 0; r < 16; r++) acc[j][r] = 0.f;

    for (int k0 = 0; k0 < DI; k0 += 512) {
        __syncthreads();
        for (int j = t; j < 16 * 512; j += 256) {
            int r = j >> 9, kk = j & 511;
            down_s[r * 512 + dswz(kk)] = dwb[r * DI + k0 + kk];
        }
        __syncthreads();
        const int gk = k0 + ks;
        #pragma unroll
        for (int j = 0; j < 2; j++) {
            const float* xr = x + (size_t)(rowbase + j) * DI + gk;
            float4 v0 = rna4(*reinterpret_cast<const float4*>(xr));
            float4 v1 = rna4(*reinterpret_cast<const float4*>(xr + 4));
            float4 v2 = rna4(*reinterpret_cast<const float4*>(xr + 8));
            float4 v3 = rna4(*reinterpret_cast<const float4*>(xr + 12));
            transpose_store_16(g_xp + (size_t)(rowbase + j) * DI + gk, v0, v1, v2, v3);
            #pragma unroll
            for (int r = 0; r < 16; r++) {
                const float* dr = down_s + r * 512;
                float4 d0 = *reinterpret_cast<const float4*>(dr + o0);
                float4 d1 = *reinterpret_cast<const float4*>(dr + o1);
                float4 d2 = *reinterpret_cast<const float4*>(dr + o2);
                float4 d3 = *reinterpret_cast<const float4*>(dr + o3);
                acc[j][r] += v0.x * d0.x + v0.y * d0.y + v0.z * d0.z + v0.w * d0.w
                           + v1.x * d1.x + v1.y * d1.y + v1.z * d1.z + v1.w * d1.w
                           + v2.x * d2.x + v2.y * d2.y + v2.z * d2.z + v2.w * d2.w
                           + v3.x * d3.x + v3.y * d3.y + v3.z * d3.z + v3.w * d3.w;
            }
        }
    }
    #pragma unroll
    for (int j = 0; j < 2; j++) {
        #pragma unroll
        for (int r = 0; r < 16; r++) {
            float v = acc[j][r];
            v += __shfl_xor_sync(~0u, v, 16);
            v += __shfl_xor_sync(~0u, v, 8);
            v += __shfl_xor_sync(~0u, v, 4);
            v += __shfl_xor_sync(~0u, v, 2);
            v += __shfl_xor_sync(~0u, v, 1);
            if (l == 0) {
                int pos = (r & 3) * 4 + (r >> 2);
                g_lrp[(size_t)(rowbase + j) * 32 + pos] = rna_tf32(v);
            }
        }
        if (l < 16) g_lrp[(size_t)(rowbase + j) * 32 + 16 + l] = 0.f;
    }
}

// ------------------------------- main GEMM ----------------------------------
// 256 threads, 8 warps (2x4), warp tile 64x64.
DEVFN void load_stage(int chunk, uint32_t sA, int m0, int n0, int bb) {
    const uint32_t sB = sA + A_BYTES;
    const int t = threadIdx.x;
    const float *ap, *bp;
    size_t str;
    if (chunk < NCHUNK) {
        ap = g_xp + (size_t)m0 * DI + chunk * KC;
        bp = g_wp + (size_t)n0 * DI + chunk * KC;
        str = DI;
    } else {
        ap = g_lrp + (size_t)m0 * 32;
        bp = g_upp + ((size_t)bb * DO + n0) * 32;
        str = 32;
    }
    #pragma unroll
    for (int q = 0; q < 4; q++) {                       // A: 1024 chunks16
        int idx = t + q * 256, row = idx >> 3, ch = idx & 7;
        cp_async16(sA + row * 128 + (uint32_t)((ch ^ SWZ(row)) << 4),
                   ap + (size_t)row * str + ch * 4);
    }
    #pragma unroll
    for (int q = 0; q < 8; q++) {                       // B: 2048 chunks16
        int idx = t + q * 256, row = idx >> 3, ch = idx & 7;
        cp_async16(sB + row * 128 + (uint32_t)((ch ^ SWZ(row)) << 4),
                   bp + (size_t)row * str + ch * 4);
    }
}

__global__ void __launch_bounds__(256, 1)
gemm_kernel(const float* __restrict__ bias, float* __restrict__ out) {
    extern __shared__ char smem_raw[];
    float* bias_s = reinterpret_cast<float*>(smem_raw);   // 256 floats
    const uint32_t stage_u = s2u(smem_raw + 1024);

    const int t = threadIdx.x;
    const int wid = t >> 5, lane = t & 31;
    const int gID = lane >> 2, g = lane & 3;
    const int warpM = wid >> 2, warpN = wid & 3;          // 2 x 4 warps, 64x64 tiles

    const int n0 = blockIdx.x * TN;
    const int m0 = blockIdx.y * TM;
    const int bb = m0 / SEQ;

    bias_s[t] = bias[n0 + t];

    float acc[4][8][4];
    #pragma unroll
    for (int mf = 0; mf < 4; mf++)
        #pragma unroll
        for (int nf = 0; nf < 8; nf++)
            #pragma unroll
            for (int k = 0; k < 4; k++) acc[mf][nf][k] = 0.f;

    load_stage(0, stage_u + 0 * STAGE_BYTES, m0, n0, bb); CP_COMMIT();
    load_stage(1, stage_u + 1 * STAGE_BYTES, m0, n0, bb); CP_COMMIT();
    load_stage(2, stage_u + 2 * STAGE_BYTES, m0, n0, bb); CP_COMMIT();

    for (int c = 0; c <= NCHUNK; c++) {
        int rem = NCHUNK - c;
        if (rem >= 2)      asm volatile("cp.async.wait_group 2;" ::: "memory");
        else if (rem == 1) asm volatile("cp.async.wait_group 1;" ::: "memory");
        else               asm volatile("cp.async.wait_group 0;" ::: "memory");
        __syncthreads();
        if (c + 3 <= NCHUNK) {
            load_stage(c + 3, stage_u + ((c + 3) & 3) * STAGE_BYTES, m0, n0, bb);
            CP_COMMIT();
        }
        const uint32_t sAc = stage_u + (c & 3) * STAGE_BYTES;
        const uint32_t sBc = sAc + A_BYTES;
        #pragma unroll
        for (int G = 0; G < 2; G++) {
            const uint32_t cw = (uint32_t)(4 * G + g);
            float4 Af[4][2];
            #pragma unroll
            for (int mf = 0; mf < 4; mf++)
                #pragma unroll
                for (int rr = 0; rr < 2; rr++) {
                    int row = warpM * 64 + mf * 16 + rr * 8 + gID;
                    Af[mf][rr] = lds_v4(sAc + row * 128 + ((cw ^ SWZ(row)) << 4));
                }
            #pragma unroll
            for (int half = 0; half < 2; half++) {
                float4 Bf[4];
                #pragma unroll
                for (int j = 0; j < 4; j++) {
                    int row = warpN * 64 + (half * 4 + j) * 8 + gID;
                    Bf[j] = lds_v4(sBc + row * 128 + ((cw ^ SWZ(row)) << 4));
                }
                #pragma unroll
                for (int mf = 0; mf < 4; mf++)
                    #pragma unroll
                    for (int j = 0; j < 4; j++) {
                        float* d = acc[mf][half * 4 + j];
                        mma8(d, Af[mf][0].x, Af[mf][1].x, Af[mf][0].y, Af[mf][1].y,
                             Bf[j].x, Bf[j].y);
                        mma8(d, Af[mf][0].z, Af[mf][1].z, Af[mf][0].w, Af[mf][1].w,
                             Bf[j].z, Bf[j].w);
                    }
            }
        }
    }

    // epilogue: c0:(gID, 2g) c1:(gID, 2g+1) c2:(gID+8, 2g) c3:(gID+8, 2g+1)
    #pragma unroll
    for (int mf = 0; mf < 4; mf++) {
        const int r0 = m0 + warpM * 64 + mf * 16 + gID;
        #pragma unroll
        for (int nf = 0; nf < 8; nf++) {
            const int col = warpN * 64 + nf * 8 + 2 * g;
            const float b0 = bias_s[col], b1 = bias_s[col + 1];
            float2 v0, v1;
            v0.x = acc[mf][nf][0] + b0; v0.y = acc[mf][nf][1] + b1;
            v1.x = acc[mf][nf][2] + b0; v1.y = acc[mf][nf][3] + b1;
            *reinterpret_cast<float2*>(out + (size_t)r0 * DO + n0 + col) = v0;
            *reinterpret_cast<float2*>(out + (size_t)(r0 + 8) * DO + n0 + col) = v1;
        }
    }
}

// ------------------------------- launch -------------------------------------
extern "C" void kernel_launch(void* const* d_in, const int* /*in_sizes*/, int /*n_in*/,
                              void* d_out, int /*out_size*/) {
    const float* x  = (const float*)d_in[0];
    const float* W  = (const float*)d_in[1];
    const float* b  = (const float*)d_in[2];
    const float* da = (const float*)d_in[3];
    const float* ua = (const float*)d_in[4];
    const float* hd = (const float*)d_in[5];
    const float* hu = (const float*)d_in[6];
    float* out = (float*)d_out;

    cudaFuncSetAttribute(gemm_kernel, cudaFuncAttributeMaxDynamicSharedMemorySize, SMEM_BYTES);

    prep_all_kernel<<<7168, 256>>>(da, ua, hd, hu, reinterpret_cast<const float4*>(W));
    lowrank_kernel<<<MTOT / 16, 256>>>(x);
    gemm_kernel<<<dim3(DO / TN, MTOT / TM), 256, SMEM_BYTES>>>(b, out);
}

// round 6
// speedup vs baseline: 2.1011x; 1.8868x over previous
#include <cuda_runtime.h>
#include <cuda_fp16.h>
#include <cstdint>
#include <cstddef>

constexpr int BATCH = 4, SEQ = 2048, DI = 4096, DO = 4096, RANK = 16;
constexpr int MTOT = BATCH * SEQ;          // 8192
constexpr float LORA_SCALE = 2.0f;         // ALPHA / RANK

constexpr int TM = 128, TN = 256, KC = 64; // K-chunk = 64 fp16 = 128B rows
constexpr int STAGES = 4;
constexpr int NCHUNK = DI / KC;            // 64 real chunks; chunk 64 = LoRA chunk
constexpr int A_BYTES = TM * 128;          // 16 KB
constexpr int B_BYTES = TN * 128;          // 32 KB
constexpr int STAGE_BYTES = A_BYTES + B_BYTES;           // 48 KB
constexpr int SMEM_BYTES = 1024 + STAGES * STAGE_BYTES;  // 197632

// Row swizzle over 16B chunk index (3 bits), conflict-free for v4 frag loads.
#define SWZ(r) (((((r) & 1) << 2) | (((r) >> 1) & 3)))

// ---------------- scratch (__device__ globals: allocation-free) -------------
// fp16 operands, permuted per 64-k group:
// pos(k) = s*32 + g*8 + G*4 + hi8*2 + e, where s=k>>5, kk=k&31, G=(kk>>4)&1,
// r=kk&15, hi8=r>>3, g=(r&7)>>1, e=k&1.
// Thread g then loads 8 consecutive fp16 (one v4.b32) = full A/B fragment data
// for BOTH k16 steps of super-group s.
__device__ __align__(128) __half g_xp[(size_t)MTOT * DI];
__device__ __align__(128) __half g_wp[(size_t)DO * DI];
__device__ __align__(128) float  g_downw[BATCH * RANK * DI];      // fp32, scale folded
__device__ __align__(128) __half g_upp[(size_t)BATCH * DO * 64];  // K padded 64, perm
__device__ __align__(128) __half g_lrp[(size_t)MTOT * 64];        // K padded 64, perm

#define DEVFN __device__ __forceinline__

DEVFN uint32_t s2u(const void* p) {
    uint32_t a;
    asm("{ .reg .u64 t; cvta.to.shared.u64 t, %1; cvt.u32.u64 %0, t; }" : "=r"(a) : "l"(p));
    return a;
}
DEVFN void cp_async16(uint32_t dst, const void* src) {
    unsigned long long g = (unsigned long long)__cvta_generic_to_global((void*)src);
    asm volatile("cp.async.cg.shared.global [%0], [%1], 16;" :: "r"(dst), "l"(g));
}
#define CP_COMMIT() asm volatile("cp.async.commit_group;" ::: "memory")

DEVFN uint4 lds_v4u(uint32_t addr) {
    uint4 v;
    asm volatile("ld.shared.v4.b32 {%0,%1,%2,%3}, [%4];"
                 : "=r"(v.x), "=r"(v.y), "=r"(v.z), "=r"(v.w) : "r"(addr));
    return v;
}

// D += A*B, m16n8k16 fp16 inputs, fp32 accumulate.
DEVFN void mma16(float* d, uint32_t a0, uint32_t a1, uint32_t a2, uint32_t a3,
                 uint32_t b0, uint32_t b1) {
    asm volatile("mma.sync.aligned.m16n8k16.row.col.f32.f16.f16.f32 "
                 "{%0,%1,%2,%3}, {%4,%5,%6,%7}, {%8,%9}, {%0,%1,%2,%3};"
                 : "+f"(d[0]), "+f"(d[1]), "+f"(d[2]), "+f"(d[3])
                 : "r"(a0), "r"(a1), "r"(a2), "r"(a3), "r"(b0), "r"(b1));
}

DEVFN uint32_t h2u(__half2 h) { return *reinterpret_cast<uint32_t*>(&h); }

// ------------------------- merged prep kernel -------------------------------
// blocks [0,64): down factors; [64,128): up factors; [128,1152): W convert
__global__ __launch_bounds__(256) void prep_all_kernel(
    const float* __restrict__ da, const float* __restrict__ ua,
    const float* __restrict__ hd, const float* __restrict__ hu,
    const float* __restrict__ W)
{
    __shared__ float hs[1024];
    const int bid = blockIdx.x, t = threadIdx.x;
    if (bid < 64) {
        // down[b][r][i] = scale * sum_a da[i,a] * hd[b,a,r]
        const int b = bid >> 4;
        const int i = (bid & 15) * 256 + t;
        for (int j = t; j < 1024; j += 256) hs[j] = hd[b * 1024 + j];  // hs[a*16+r]
        __syncthreads();
        float acc[16];
        #pragma unroll
        for (int r = 0; r < 16; r++) acc[r] = 0.f;
        const float4* dap = reinterpret_cast<const float4*>(da + (size_t)i * 64);
        #pragma unroll 4
        for (int aq = 0; aq < 16; aq++) {
            float4 v = dap[aq];
            #pragma unroll
            for (int r = 0; r < 16; r++)
                acc[r] += v.x * hs[(aq * 4 + 0) * 16 + r] + v.y * hs[(aq * 4 + 1) * 16 + r]
                        + v.z * hs[(aq * 4 + 2) * 16 + r] + v.w * hs[(aq * 4 + 3) * 16 + r];
        }
        #pragma unroll
        for (int r = 0; r < 16; r++)
            g_downw[((size_t)b * RANK + r) * DI + i] = LORA_SCALE * acc[r];
    } else if (bid < 128) {
        // up[b][o][c] = sum_a ua[a,o] * hu[b,c,a]; store fp16 permuted+padded
        const int bb2 = bid - 64;
        const int b = bb2 >> 4;
        const int o = (bb2 & 15) * 256 + t;
        for (int j = t; j < 1024; j += 256) hs[j] = hu[b * 1024 + j];  // hs[c*64+a]
        __syncthreads();
        float acc[16];
        #pragma unroll
        for (int c = 0; c < 16; c++) acc[c] = 0.f;
        #pragma unroll 4
        for (int a = 0; a < 64; a++) {
            float uv = ua[(size_t)a * DO + o];
            #pragma unroll
            for (int c = 0; c < 16; c++) acc[c] += uv * hs[c * 64 + a];
        }
        __half* op = g_upp + ((size_t)b * DO + o) * 64;
        #pragma unroll
        for (int q = 0; q < 4; q++) {
            uint2 v;
            v.x = h2u(__floats2half2_rn(acc[2 * q], acc[2 * q + 1]));
            v.y = h2u(__floats2half2_rn(acc[2 * q + 8], acc[2 * q + 9]));
            *reinterpret_cast<uint2*>(op + q * 8) = v;                 // data chunks
            *reinterpret_cast<uint2*>(op + q * 8 + 4) = make_uint2(0, 0);
        }
        #pragma unroll
        for (int q = 0; q < 4; q++)
            *reinterpret_cast<uint4*>(op + 32 + q * 8) = make_uint4(0, 0, 0, 0);
    } else {
        // W: one 64-group per thread, fp16 + permute
        const size_t i = (size_t)(bid - 128) * 256 + t;
        const float* wp = W + i * 64;
        float v[64];
        #pragma unroll
        for (int q = 0; q < 16; q++) {
            float4 f = reinterpret_cast<const float4*>(wp)[q];
            v[4 * q] = f.x; v[4 * q + 1] = f.y; v[4 * q + 2] = f.z; v[4 * q + 3] = f.w;
        }
        __half* op = g_wp + i * 64;
        #pragma unroll
        for (int s = 0; s < 2; s++)
            #pragma unroll
            for (int g4 = 0; g4 < 4; g4++) {
                const int kb = s * 32;
                uint4 u;
                u.x = h2u(__floats2half2_rn(v[kb + 2 * g4],      v[kb + 2 * g4 + 1]));
                u.y = h2u(__floats2half2_rn(v[kb + 8 + 2 * g4],  v[kb + 9 + 2 * g4]));
                u.z = h2u(__floats2half2_rn(v[kb + 16 + 2 * g4], v[kb + 17 + 2 * g4]));
                u.w = h2u(__floats2half2_rn(v[kb + 24 + 2 * g4], v[kb + 25 + 2 * g4]));
                *reinterpret_cast<uint4*>(op + s * 32 + g4 * 8) = u;
            }
    }
}

// smem swizzle for down_s: XOR 16B-chunk index with (chunk>>3)&7
DEVFN int dswz(int kk) {
    int c = kk >> 2;
    return ((c ^ ((c >> 3) & 7)) << 2) | (kk & 3);
}

// Fused: x -> fp16+perm copy AND low_rank = x @ down^T (scale folded in down).
__global__ __launch_bounds__(256) void lowrank_kernel(const float* __restrict__ x) {
    __shared__ float down_s[16 * 512];
    const int m0 = blockIdx.x * 16;
    const int bb = m0 / SEQ;
    const int t = threadIdx.x, w = t >> 5, l = t & 31;
    const int rowbase = m0 + w * 2;
    const float* dwb = g_downw + (size_t)bb * RANK * DI;

    const int ks = l * 16;
    const int o0 = dswz(ks), o1 = dswz(ks + 4), o2 = dswz(ks + 8), o3 = dswz(ks + 12);

    float acc[2][16];
    #pragma unroll
    for (int j = 0; j < 2; j++)
        #pragma unroll
        for (int r = 0; r < 16; r++) acc[j][r] = 0.f;

    for (int k0 = 0; k0 < DI; k0 += 512) {
        __syncthreads();
        for (int j = t; j < 16 * 512; j += 256) {
            int r = j >> 9, kk = j & 511;
            down_s[r * 512 + dswz(kk)] = dwb[r * DI + k0 + kk];
        }
        __syncthreads();
        const int gk = k0 + ks;
        // permute target: 16 consecutive k with fixed s,G
        const int grp = gk & ~63, off = gk & 63;
        const int sb = ((off >> 5) & 1) * 32 + ((off >> 4) & 1) * 4;
        #pragma unroll
        for (int j = 0; j < 2; j++) {
            const float* xr = x + (size_t)(rowbase + j) * DI + gk;
            float v[16];
            #pragma unroll
            for (int q = 0; q < 4; q++) {
                float4 f = reinterpret_cast<const float4*>(xr)[q];
                v[4 * q] = f.x; v[4 * q + 1] = f.y; v[4 * q + 2] = f.z; v[4 * q + 3] = f.w;
            }
            __half* op = g_xp + (size_t)(rowbase + j) * DI + grp + sb;
            #pragma unroll
            for (int g4 = 0; g4 < 4; g4++) {
                uint2 u;
                u.x = h2u(__floats2half2_rn(v[2 * g4], v[2 * g4 + 1]));
                u.y = h2u(__floats2half2_rn(v[8 + 2 * g4], v[9 + 2 * g4]));
                *reinterpret_cast<uint2*>(op + g4 * 8) = u;
            }
            #pragma unroll
            for (int r = 0; r < 16; r++) {
                const float* dr = down_s + r * 512;
                float4 d0 = *reinterpret_cast<const float4*>(dr + o0);
                float4 d1 = *reinterpret_cast<const float4*>(dr + o1);
                float4 d2 = *reinterpret_cast<const float4*>(dr + o2);
                float4 d3 = *reinterpret_cast<const float4*>(dr + o3);
                acc[j][r] += v[0] * d0.x + v[1] * d0.y + v[2] * d0.z + v[3] * d0.w
                           + v[4] * d1.x + v[5] * d1.y + v[6] * d1.z + v[7] * d1.w
                           + v[8] * d2.x + v[9] * d2.y + v[10] * d2.z + v[11] * d2.w
                           + v[12] * d3.x + v[13] * d3.y + v[14] * d3.z + v[15] * d3.w;
            }
        }
    }
    #pragma unroll
    for (int j = 0; j < 2; j++) {
        #pragma unroll
        for (int r = 0; r < 16; r++) {
            float v = acc[j][r];
            v += __shfl_xor_sync(~0u, v, 16);
            v += __shfl_xor_sync(~0u, v, 8);
            v += __shfl_xor_sync(~0u, v, 4);
            v += __shfl_xor_sync(~0u, v, 2);
            v += __shfl_xor_sync(~0u, v, 1);
            acc[j][r] = v;   // lane0 has the sum
        }
        if (l == 0) {
            __half* op = g_lrp + (size_t)(rowbase + j) * 64;
            #pragma unroll
            for (int q = 0; q < 4; q++) {
                uint2 u;
                u.x = h2u(__floats2half2_rn(acc[j][2 * q], acc[j][2 * q + 1]));
                u.y = h2u(__floats2half2_rn(acc[j][2 * q + 8], acc[j][2 * q + 9]));
                *reinterpret_cast<uint2*>(op + q * 8) = u;
                *reinterpret_cast<uint2*>(op + q * 8 + 4) = make_uint2(0, 0);
            }
            #pragma unroll
            for (int q = 0; q < 4; q++)
                *reinterpret_cast<uint4*>(op + 32 + q * 8) = make_uint4(0, 0, 0, 0);
        }
    }
}

// ------------------------------- main GEMM ----------------------------------
// 256 threads, 8 warps (2x4), warp tile 64x64, fp16 m16n8k16.
DEVFN void load_stage(int chunk, uint32_t sA, int m0, int n0, int bb) {
    const uint32_t sB = sA + A_BYTES;
    const int t = threadIdx.x;
    const __half *ap, *bp;
    size_t str;
    if (chunk < NCHUNK) {
        ap = g_xp + (size_t)m0 * DI + chunk * KC;
        bp = g_wp + (size_t)n0 * DI + chunk * KC;
        str = DI;
    } else {
        ap = g_lrp + (size_t)m0 * 64;
        bp = g_upp + ((size_t)bb * DO + n0) * 64;
        str = 64;
    }
    #pragma unroll
    for (int q = 0; q < 4; q++) {                       // A: 1024 chunks16
        int idx = t + q * 256, row = idx >> 3, ch = idx & 7;
        cp_async16(sA + row * 128 + (uint32_t)((ch ^ SWZ(row)) << 4),
                   ap + (size_t)row * str + ch * 8);
    }
    #pragma unroll
    for (int q = 0; q < 8; q++) {                       // B: 2048 chunks16
        int idx = t + q * 256, row = idx >> 3, ch = idx & 7;
        cp_async16(sB + row * 128 + (uint32_t)((ch ^ SWZ(row)) << 4),
                   bp + (size_t)row * str + ch * 8);
    }
}

__global__ void __launch_bounds__(256, 1)
gemm_kernel(const float* __restrict__ bias, float* __restrict__ out) {
    extern __shared__ char smem_raw[];
    float* bias_s = reinterpret_cast<float*>(smem_raw);   // 256 floats
    const uint32_t stage_u = s2u(smem_raw + 1024);

    const int t = threadIdx.x;
    const int wid = t >> 5, lane = t & 31;
    const int gID = lane >> 2, g = lane & 3;
    const int warpM = wid >> 2, warpN = wid & 3;          // 2 x 4 warps, 64x64 tiles

    const int n0 = blockIdx.x * TN;
    const int m0 = blockIdx.y * TM;
    const int bb = m0 / SEQ;

    bias_s[t] = bias[n0 + t];

    float acc[4][8][4];
    #pragma unroll
    for (int mf = 0; mf < 4; mf++)
        #pragma unroll
        for (int nf = 0; nf < 8; nf++)
            #pragma unroll
            for (int k = 0; k < 4; k++) acc[mf][nf][k] = 0.f;

    load_stage(0, stage_u + 0 * STAGE_BYTES, m0, n0, bb); CP_COMMIT();
    load_stage(1, stage_u + 1 * STAGE_BYTES, m0, n0, bb); CP_COMMIT();
    load_stage(2, stage_u + 2 * STAGE_BYTES, m0, n0, bb); CP_COMMIT();

    for (int c = 0; c <= NCHUNK; c++) {
        int rem = NCHUNK - c;
        if (rem >= 2)      asm volatile("cp.async.wait_group 2;" ::: "memory");
        else if (rem == 1) asm volatile("cp.async.wait_group 1;" ::: "memory");
        else               asm volatile("cp.async.wait_group 0;" ::: "memory");
        __syncthreads();
        if (c + 3 <= NCHUNK) {
            load_stage(c + 3, stage_u + ((c + 3) & 3) * STAGE_BYTES, m0, n0, bb);
            CP_COMMIT();
        }
        const uint32_t sAc = stage_u + (c & 3) * STAGE_BYTES;
        const uint32_t sBc = sAc + A_BYTES;
        #pragma unroll
        for (int s = 0; s < 2; s++) {
            const uint32_t cw = (uint32_t)(4 * s + g);
            uint4 A0[4], A1[4];
            #pragma unroll
            for (int mf = 0; mf < 4; mf++) {
                int row0 = warpM * 64 + mf * 16 + gID;
                int row1 = row0 + 8;
                A0[mf] = lds_v4u(sAc + row0 * 128 + ((cw ^ SWZ(row0)) << 4));
                A1[mf] = lds_v4u(sAc + row1 * 128 + ((cw ^ SWZ(row1)) << 4));
            }
            #pragma unroll
            for (int half = 0; half < 2; half++) {
                uint4 Bf[4];
                #pragma unroll
                for (int j = 0; j < 4; j++) {
                    int row = warpN * 64 + (half * 4 + j) * 8 + gID;
                    Bf[j] = lds_v4u(sBc + row * 128 + ((cw ^ SWZ(row)) << 4));
                }
                #pragma unroll
                for (int mf = 0; mf < 4; mf++)
                    #pragma unroll
                    for (int j = 0; j < 4; j++) {
                        float* d = acc[mf][half * 4 + j];
                        mma16(d, A0[mf].x, A1[mf].x, A0[mf].y, A1[mf].y,
                              Bf[j].x, Bf[j].y);                       // k16 step G0
                        mma16(d, A0[mf].z, A1[mf].z, A0[mf].w, A1[mf].w,
                              Bf[j].z, Bf[j].w);                       // k16 step G1
                    }
            }
        }
    }

    // epilogue: c0:(gID, 2g) c1:(gID, 2g+1) c2:(gID+8, 2g) c3:(gID+8, 2g+1)
    #pragma unroll
    for (int mf = 0; mf < 4; mf++) {
        const int r0 = m0 + warpM * 64 + mf * 16 + gID;
        #pragma unroll
        for (int nf = 0; nf < 8; nf++) {
            const int col = warpN * 64 + nf * 8 + 2 * g;
            const float b0 = bias_s[col], b1 = bias_s[col + 1];
            float2 v0, v1;
            v0.x = acc[mf][nf][0] + b0; v0.y = acc[mf][nf][1] + b1;
            v1.x = acc[mf][nf][2] + b0; v1.y = acc[mf][nf][3] + b1;
            *reinterpret_cast<float2*>(out + (size_t)r0 * DO + n0 + col) = v0;
            *reinterpret_cast<float2*>(out + (size_t)(r0 + 8) * DO + n0 + col) = v1;
        }
    }
}

// ------------------------------- launch -------------------------------------
extern "C" void kernel_launch(void* const* d_in, const int* /*in_sizes*/, int /*n_in*/,
                              void* d_out, int /*out_size*/) {
    const float* x  = (const float*)d_in[0];
    const float* W  = (const float*)d_in[1];
    const float* b  = (const float*)d_in[2];
    const float* da = (const float*)d_in[3];
    const float* ua = (const float*)d_in[4];
    const float* hd = (const float*)d_in[5];
    const float* hu = (const float*)d_in[6];
    float* out = (float*)d_out;

    cudaFuncSetAttribute(gemm_kernel, cudaFuncAttributeMaxDynamicSharedMemorySize, SMEM_BYTES);

    prep_all_kernel<<<1152, 256>>>(da, ua, hd, hu, W);
    lowrank_kernel<<<MTOT / 16, 256>>>(x);
    gemm_kernel<<<dim3(DO / TN, MTOT / TM), 256, SMEM_BYTES>>>(b, out);
}